// round 14
// baseline (speedup 1.0000x reference)
#include <cuda_runtime.h>
#include <cuda_bf16.h>
#include <math.h>

// Problem constants
static constexpr int NB = 16;           // B_Nq == B_Ns
static constexpr int NC = 512;          // C
static constexpr int NP = 1024;         // H*W
static constexpr long CP = (long)NC * NP;            // 524288
static constexpr long OUT_ALPHA = (long)NB * CP;     // 8388608
static constexpr long OUT_BETA  = OUT_ALPHA + (long)NB * NP;

// Scratch (device globals; allocation-free kernel_launch)
__device__ float          g_fsmean[NC * NP];          // mean_b f_s (fp32)
__device__ __nv_bfloat16  g_fsmean_h[NC * NP];        // bf16 [d,p] (GEMM1 B)
__device__ __nv_bfloat16  g_fsvT[NP * NC];            // bf16 [p,d] = wv[d]*fsmean[d,p]
__device__ __nv_bfloat16  g_Sh[(long)NB * NC * NC];   // softmaxed Ac (bf16)
__device__ float          g_ksbar[NC];
__device__ float          g_rm_part[NB * 4 * NP];
__device__ float          g_qb_part[NB * 8 * NC];
__device__ float          g_beta[NB * NP];            // beta

// ---------------------------------------------------------------------------
// PTX helpers
// ---------------------------------------------------------------------------
__device__ __forceinline__ unsigned sptr(const void* p) {
    return (unsigned)__cvta_generic_to_shared(p);
}
__device__ __forceinline__ void ldsm_x4(unsigned& r0, unsigned& r1, unsigned& r2, unsigned& r3,
                                        unsigned addr) {
    asm volatile("ldmatrix.sync.aligned.m8n8.x4.shared.b16 {%0,%1,%2,%3}, [%4];"
                 : "=r"(r0), "=r"(r1), "=r"(r2), "=r"(r3) : "r"(addr));
}
__device__ __forceinline__ void mma_bf16(float c[4], const unsigned a[4], const unsigned b[2]) {
    asm volatile(
        "mma.sync.aligned.m16n8k16.row.col.f32.bf16.bf16.f32 "
        "{%0,%1,%2,%3}, {%4,%5,%6,%7}, {%8,%9}, {%0,%1,%2,%3};"
        : "+f"(c[0]), "+f"(c[1]), "+f"(c[2]), "+f"(c[3])
        : "r"(a[0]), "r"(a[1]), "r"(a[2]), "r"(a[3]), "r"(b[0]), "r"(b[1]));
}
__device__ __forceinline__ void cpa16(const void* s, const void* g) {
    unsigned saddr = sptr(s);
    asm volatile("cp.async.cg.shared.global [%0], [%1], 16;" :: "r"(saddr), "l"(g));
}
__device__ __forceinline__ void cpa_commit() { asm volatile("cp.async.commit_group;"); }
__device__ __forceinline__ void cpa_wait2()  { asm volatile("cp.async.wait_group 2;"); }
__device__ __forceinline__ void cpa_wait1()  { asm volatile("cp.async.wait_group 1;"); }
__device__ __forceinline__ void cpa_wait0()  { asm volatile("cp.async.wait_group 0;"); }

__device__ __forceinline__ unsigned pack_bf2(float lo, float hi) {
    __nv_bfloat162 h = __floats2bfloat162_rn(lo, hi);
    return *(unsigned*)&h;
}

// ---------------------------------------------------------------------------
// Stage 1 (prep): block == one channel row c. fs_mean, bf16 copy, ksbar.
// ---------------------------------------------------------------------------
__global__ __launch_bounds__(256) void k_prep(const float* __restrict__ fs,
                                              const float* __restrict__ wsk) {
    const int c = blockIdx.x;
    const int t = threadIdx.x;
    const int i4 = c * 256 + t;
    const float4* f4 = (const float4*)fs;
    float4 a = make_float4(0.f, 0.f, 0.f, 0.f);
#pragma unroll
    for (int b = 0; b < NB; b++) {
        float4 v = f4[(long)b * (CP / 4) + i4];
        a.x += v.x; a.y += v.y; a.z += v.z; a.w += v.w;
    }
    const float s = 1.0f / (float)NB;
    a.x *= s; a.y *= s; a.z *= s; a.w *= s;
    ((float4*)g_fsmean)[i4] = a;
    ((uint2*)g_fsmean_h)[i4] = make_uint2(pack_bf2(a.x, a.y), pack_bf2(a.z, a.w));

    float rs = a.x + a.y + a.z + a.w;
    __shared__ float sh[8];
#pragma unroll
    for (int o = 16; o; o >>= 1) rs += __shfl_xor_sync(0xffffffffu, rs, o);
    if ((t & 31) == 0) sh[t >> 5] = rs;
    __syncthreads();
    if (t == 0) {
        float tot = 0.f;
#pragma unroll
        for (int i = 0; i < 8; i++) tot += sh[i];
        g_ksbar[c] = wsk[c] * tot * (1.0f / (float)NP);
    }
}

// ---------------------------------------------------------------------------
// Stage 1c: fsvT[p,d] = wv[d]*fsmean[d,p]  (bf16, K-major for GEMM2 B)
// ---------------------------------------------------------------------------
__global__ __launch_bounds__(256) void k_trans(const float* __restrict__ wv) {
    __shared__ float tile[32][33];
    const int p0 = blockIdx.x * 32, d0 = blockIdx.y * 32;
    const int tx = threadIdx.x & 31, ty = threadIdx.x >> 5;   // ty 0..7
#pragma unroll
    for (int r = 0; r < 4; r++) {
        const int d = d0 + ty + r * 8;
        tile[ty + r * 8][tx] = g_fsmean[(long)d * NP + p0 + tx] * wv[d];
    }
    __syncthreads();
#pragma unroll
    for (int r = 0; r < 4; r++) {
        const int p = p0 + ty + r * 8;
        g_fsvT[(long)p * NC + d0 + tx] = __float2bfloat16_rn(tile[tx][ty + r * 8]);
    }
}

// ---------------------------------------------------------------------------
// Stage 2: FUSED GEMM1 + row softmax (round-7 proven, exact revert).
//   CTA tile 64(c) x 512(d), 512 threads (16 warps: wm=w&1, wn=w>>1).
// ---------------------------------------------------------------------------
static constexpr int G1_BKH = 40;                       // padded halves per row
static constexpr int G1_AH = 64 * G1_BKH;               // 2560 halves / A stage
static constexpr int G1_BH = 512 * G1_BKH;              // 20480 halves / B stage
static constexpr int G1_STG_H = G1_AH + G1_BH;          // 23040
static constexpr int G1_SMEM = 3 * G1_STG_H * 2 + 4096; // + softmax red buffers

__global__ __launch_bounds__(512, 1) void k_gemm1f(const float* __restrict__ fq,
                                                   const float* __restrict__ wq,
                                                   const float* __restrict__ wk) {
    extern __shared__ __align__(16) __nv_bfloat16 smh[];
    const int b  = blockIdx.y;
    const int m0 = blockIdx.x * 64;
    const float* A = fq + (long)b * CP + (long)m0 * NP;
    const __nv_bfloat16* B = g_fsmean_h;
    const int t = threadIdx.x;
    const int w = t >> 5, l = t & 31;
    const int wm = w & 1, wn = w >> 1;     // 2 x 8 warp grid
    const int r = l >> 2, q = l & 3;

    unsigned aoff[2], boff[4];
#pragma unroll
    for (int mi = 0; mi < 2; mi++)
        aoff[mi] = ((wm * 32 + mi * 16 + (l & 15)) * G1_BKH + (l >> 4) * 8) * 2;
#pragma unroll
    for (int g = 0; g < 4; g++)
        boff[g] = ((wn * 64 + g * 16 + ((l >> 4) << 3) + (l & 7)) * G1_BKH + ((l >> 3) & 1) * 8) * 2;
    const unsigned smb = sptr(smh);

    const int arow = t >> 3, akc = (t & 7) * 4;
    float acc[2][8][4] = {};

    auto ldA = [&](int k0) -> float4 {
        return *(const float4*)(A + (long)arow * NP + k0 + akc);
    };
    auto stA = [&](int stg, float4 v) {
        *(uint2*)((char*)(smh + stg * G1_STG_H) + (arow * G1_BKH + akc) * 2) =
            make_uint2(pack_bf2(v.x, v.y), pack_bf2(v.z, v.w));
    };
    auto ldB = [&](int stg, int k0) {
        __nv_bfloat16* bs = smh + stg * G1_STG_H + G1_AH;
#pragma unroll
        for (int u = 0; u < 4; u++) {
            const int idx = u * 512 + t;
            const int row = idx >> 2, kc = (idx & 3) * 8;
            cpa16(bs + row * G1_BKH + kc, B + (long)row * NP + k0 + kc);
        }
        cpa_commit();
    };

    const int NK = NP / 32;   // 32
    float4 a0 = ldA(0);
    ldB(0, 0);
    float4 a1 = ldA(32);
    ldB(1, 32);
    stA(0, a0);
    stA(1, a1);
    float4 ar = ldA(64);
    ldB(2, 64);

    for (int ks = 0; ks < NK; ks++) {
        const int rem = NK - 1 - ks;
        if (rem >= 2) cpa_wait2(); else if (rem == 1) cpa_wait1(); else cpa_wait0();
        __syncthreads();
        if (ks + 2 < NK) stA((ks + 2) % 3, ar);
        const int stg = ks % 3;
        const unsigned ab = smb + stg * (G1_STG_H * 2);
        const unsigned bb = ab + G1_AH * 2;
#pragma unroll
        for (int kk = 0; kk < 2; kk++) {
            unsigned af[2][4], bf[8][2];
#pragma unroll
            for (int mi = 0; mi < 2; mi++)
                ldsm_x4(af[mi][0], af[mi][1], af[mi][2], af[mi][3], ab + aoff[mi] + kk * 32);
#pragma unroll
            for (int g = 0; g < 4; g++)
                ldsm_x4(bf[2 * g][0], bf[2 * g][1], bf[2 * g + 1][0], bf[2 * g + 1][1],
                        bb + boff[g] + kk * 32);
#pragma unroll
            for (int mi = 0; mi < 2; mi++)
#pragma unroll
                for (int ni = 0; ni < 8; ni++)
                    mma_bf16(acc[mi][ni], af[mi], bf[ni]);
        }
        if (ks + 3 < NK) ar = ldA((ks + 3) * 32);
        if (ks + 2 < NK) ldB((ks + 2) % 3, (ks + 2) * 32);
    }

    // ---- fused softmax epilogue ----
    float* red  = (float*)(smh + 3 * G1_STG_H);   // [64][8]
    float* red2 = red + 512;                      // [64][8]
    float rw[2][2], cw[8][2];
#pragma unroll
    for (int mi = 0; mi < 2; mi++)
#pragma unroll
    for (int h = 0; h < 2; h++)
        rw[mi][h] = wq[m0 + wm * 32 + mi * 16 + h * 8 + r] * (1.0f / (float)NP);
#pragma unroll
    for (int ni = 0; ni < 8; ni++) {
        cw[ni][0] = wk[wn * 64 + ni * 8 + q * 2 + 0];
        cw[ni][1] = wk[wn * 64 + ni * 8 + q * 2 + 1];
    }
#pragma unroll
    for (int mi = 0; mi < 2; mi++)
#pragma unroll
    for (int ni = 0; ni < 8; ni++)
#pragma unroll
    for (int h = 0; h < 2; h++) {
        acc[mi][ni][h * 2 + 0] *= rw[mi][h] * cw[ni][0];
        acc[mi][ni][h * 2 + 1] *= rw[mi][h] * cw[ni][1];
    }
#pragma unroll
    for (int mi = 0; mi < 2; mi++)
#pragma unroll
    for (int h = 0; h < 2; h++) {
        float m = acc[mi][0][h * 2];
#pragma unroll
        for (int ni = 0; ni < 8; ni++)
            m = fmaxf(m, fmaxf(acc[mi][ni][h * 2], acc[mi][ni][h * 2 + 1]));
        m = fmaxf(m, __shfl_xor_sync(0xffffffffu, m, 1));
        m = fmaxf(m, __shfl_xor_sync(0xffffffffu, m, 2));
        if (q == 0) red[(wm * 32 + mi * 16 + h * 8 + r) * 8 + wn] = m;
    }
    __syncthreads();
    float rmax[2][2];
#pragma unroll
    for (int mi = 0; mi < 2; mi++)
#pragma unroll
    for (int h = 0; h < 2; h++) {
        const float* rr = red + (wm * 32 + mi * 16 + h * 8 + r) * 8;
        float m = rr[0];
#pragma unroll
        for (int i = 1; i < 8; i++) m = fmaxf(m, rr[i]);
        rmax[mi][h] = m;
    }
#pragma unroll
    for (int mi = 0; mi < 2; mi++)
#pragma unroll
    for (int h = 0; h < 2; h++) {
        float s = 0.f;
#pragma unroll
        for (int ni = 0; ni < 8; ni++) {
            float e0 = __expf(acc[mi][ni][h * 2 + 0] - rmax[mi][h]);
            float e1 = __expf(acc[mi][ni][h * 2 + 1] - rmax[mi][h]);
            acc[mi][ni][h * 2 + 0] = e0;
            acc[mi][ni][h * 2 + 1] = e1;
            s += e0 + e1;
        }
        s += __shfl_xor_sync(0xffffffffu, s, 1);
        s += __shfl_xor_sync(0xffffffffu, s, 2);
        if (q == 0) red2[(wm * 32 + mi * 16 + h * 8 + r) * 8 + wn] = s;
    }
    __syncthreads();
    __nv_bfloat16* D = g_Sh + (long)b * NC * NC;
#pragma unroll
    for (int mi = 0; mi < 2; mi++)
#pragma unroll
    for (int h = 0; h < 2; h++) {
        const int c = m0 + wm * 32 + mi * 16 + h * 8 + r;
        const float* rr = red2 + (c - m0) * 8;
        float s = 0.f;
#pragma unroll
        for (int i = 0; i < 8; i++) s += rr[i];
        const float inv = 1.0f / s;
#pragma unroll
        for (int ni = 0; ni < 8; ni++)
            *(unsigned*)&D[(long)c * NC + wn * 64 + ni * 8 + q * 2] =
                pack_bf2(acc[mi][ni][h * 2] * inv, acc[mi][ni][h * 2 + 1] * inv);
    }
}

// ---------------------------------------------------------------------------
// Stage 4: GEMM2 (NT) bf16 — EXACT round-7 configuration (best measured).
// ---------------------------------------------------------------------------
static constexpr int BKH = 72;
static constexpr int THALF = 128 * BKH;
static constexpr int STG_H = 2 * THALF;
static constexpr int GEMM_SMEM = 3 * STG_H * 2;   // 110592 bytes

__global__ __launch_bounds__(256, 2) void k_gemm2(const float* __restrict__ fq,
                                                  const float* __restrict__ wsq,
                                                  const float* __restrict__ lamp,
                                                  float* __restrict__ out) {
    extern __shared__ __align__(16) __nv_bfloat16 smh[];
    const int b  = blockIdx.z;
    const int m0 = blockIdx.y * 128;
    const int n0 = blockIdx.x * 128;
    const __nv_bfloat16* A = g_Sh + (long)b * NC * NC;
    const __nv_bfloat16* B = g_fsvT;
    const int t = threadIdx.x;
    const int w = t >> 5, l = t & 31;
    const int wm = w & 3, wn = w >> 2;
    const int r = l >> 2, q = l & 3;

    unsigned aoff[2], boff[4];
#pragma unroll
    for (int mi = 0; mi < 2; mi++)
        aoff[mi] = ((wm * 32 + mi * 16 + (l & 15)) * BKH + (l >> 4) * 8) * 2;
#pragma unroll
    for (int g = 0; g < 4; g++)
        boff[g] = ((wn * 64 + g * 16 + ((l >> 4) << 3) + (l & 7)) * BKH + ((l >> 3) & 1) * 8) * 2;
    const unsigned smb = sptr(smh);

    float acc[2][8][4] = {};

    auto load_stage = [&](int stg, int k0) {
        __nv_bfloat16* as = smh + stg * STG_H;
        __nv_bfloat16* bs = as + THALF;
#pragma unroll
        for (int u = 0; u < 4; u++) {
            const int idx = u * 256 + t;
            const int row = idx >> 3, kc = (idx & 7) * 8;
            cpa16(as + row * BKH + kc, A + (long)(m0 + row) * NC + k0 + kc);
            cpa16(bs + row * BKH + kc, B + (long)(n0 + row) * NC + k0 + kc);
        }
        cpa_commit();
    };

    const int NK = NC / 64;   // 8
    load_stage(0, 0);
    load_stage(1, 64);

    int stg = 0;
    for (int ks = 0; ks < NK; ks++) {
        if (ks + 1 < NK) cpa_wait1(); else cpa_wait0();
        __syncthreads();
        const unsigned ab = smb + stg * (STG_H * 2);
        const unsigned bb = ab + THALF * 2;
#pragma unroll
        for (int kk = 0; kk < 4; kk++) {
            unsigned af[2][4], bf[8][2];
#pragma unroll
            for (int mi = 0; mi < 2; mi++)
                ldsm_x4(af[mi][0], af[mi][1], af[mi][2], af[mi][3], ab + aoff[mi] + kk * 32);
#pragma unroll
            for (int g = 0; g < 4; g++)
                ldsm_x4(bf[2 * g][0], bf[2 * g][1], bf[2 * g + 1][0], bf[2 * g + 1][1],
                        bb + boff[g] + kk * 32);
#pragma unroll
            for (int mi = 0; mi < 2; mi++)
#pragma unroll
                for (int ni = 0; ni < 8; ni++)
                    mma_bf16(acc[mi][ni], af[mi], bf[ni]);
        }
        if (ks + 2 < NK) load_stage((ks + 2) % 3, (ks + 2) * 64);
        stg = (stg + 1) % 3;
    }

    // ---- fused epilogue ----
    const float lam = *lamp;
    float rmloc[8][2] = {};
    float qbloc[2][2] = {};
#pragma unroll
    for (int mi = 0; mi < 2; mi++)
#pragma unroll
    for (int h = 0; h < 2; h++) {
        const int c = m0 + wm * 32 + mi * 16 + h * 8 + r;
        const float wc = wsq[c];
        const float wk2 = wc * g_ksbar[c];
        const float* fr = fq + (long)b * CP + (long)c * NP;
        float* orow = out + (long)b * CP + (long)c * NP;
        float qsum = 0.f;
#pragma unroll
        for (int ni = 0; ni < 8; ni++) {
            const int p = n0 + wn * 64 + ni * 8 + q * 2;
            const float v0 = acc[mi][ni][h * 2 + 0];
            const float v1 = acc[mi][ni][h * 2 + 1];
            const float2 f = *(const float2*)&fr[p];
            *(float2*)&orow[p] = make_float2(fmaf(lam, v0, f.x), fmaf(lam, v1, f.y));
            rmloc[ni][0] += v0 * wk2;
            rmloc[ni][1] += v1 * wk2;
            qsum += v0 + v1;
        }
        qbloc[mi][h] = qsum * wc;
    }
#pragma unroll
    for (int ni = 0; ni < 8; ni++)
#pragma unroll
    for (int j = 0; j < 2; j++) {
        float v = rmloc[ni][j];
        v += __shfl_xor_sync(0xffffffffu, v, 4);
        v += __shfl_xor_sync(0xffffffffu, v, 8);
        v += __shfl_xor_sync(0xffffffffu, v, 16);
        rmloc[ni][j] = v;
    }
#pragma unroll
    for (int mi = 0; mi < 2; mi++)
#pragma unroll
    for (int h = 0; h < 2; h++) {
        float v = qbloc[mi][h];
        v += __shfl_xor_sync(0xffffffffu, v, 1);
        v += __shfl_xor_sync(0xffffffffu, v, 2);
        qbloc[mi][h] = v;
    }
    __syncthreads();
    float* stage = (float*)smh;      // reuse smem
    float* rmstage = stage;          // [4][128]
    float* qbstage = stage + 512;    // [2][128]
    if (r == 0) {
#pragma unroll
        for (int ni = 0; ni < 8; ni++) {
            rmstage[wm * 128 + wn * 64 + ni * 8 + q * 2 + 0] = rmloc[ni][0];
            rmstage[wm * 128 + wn * 64 + ni * 8 + q * 2 + 1] = rmloc[ni][1];
        }
    }
    if (q == 0) {
#pragma unroll
        for (int mi = 0; mi < 2; mi++)
#pragma unroll
        for (int h = 0; h < 2; h++)
            qbstage[wn * 128 + wm * 32 + mi * 16 + h * 8 + r] = qbloc[mi][h];
    }
    __syncthreads();
    if (t < 128) {
        const float s = rmstage[t] + rmstage[128 + t] + rmstage[256 + t] + rmstage[384 + t];
        g_rm_part[(b * 4 + blockIdx.y) * NP + blockIdx.x * 128 + t] = s;
        const float s2 = qbstage[t] + qbstage[128 + t];
        g_qb_part[(b * 8 + blockIdx.x) * NC + blockIdx.y * 128 + t] = s2;
    }
}

// ---------------------------------------------------------------------------
// Stage 6: FUSED beta GEMV + softmax — vectorized: 256 threads, float4 per
// thread (4 p's each). Same arithmetic order per output element.
// ---------------------------------------------------------------------------
__global__ __launch_bounds__(256) void k_betafused(const float* __restrict__ wsk) {
    __shared__ float qsw[NC];
    __shared__ float sh[33];
    const int b = blockIdx.x;
    const int t = threadIdx.x;
    for (int c = t; c < NC; c += 256) {
        float s = 0.f;
#pragma unroll
        for (int nt = 0; nt < 8; nt++) s += g_qb_part[(b * 8 + nt) * NC + c];
        qsw[c] = s * (1.0f / (float)NP) * wsk[c];
    }
    __syncthreads();
    float4 a = make_float4(0.f, 0.f, 0.f, 0.f);
#pragma unroll 8
    for (int c = 0; c < NC; c++) {
        const float qv = qsw[c];
        const float4 f = *(const float4*)&g_fsmean[(long)c * NP + t * 4];
        a.x = fmaf(qv, f.x, a.x); a.y = fmaf(qv, f.y, a.y);
        a.z = fmaf(qv, f.z, a.z); a.w = fmaf(qv, f.w, a.w);
    }
    float v[4] = {a.x * (1.0f / 256.0f), a.y * (1.0f / 256.0f),
                  a.z * (1.0f / 256.0f), a.w * (1.0f / 256.0f)};
    // softmax over 1024 (4 per thread)
    float m = fmaxf(fmaxf(v[0], v[1]), fmaxf(v[2], v[3]));
#pragma unroll
    for (int o = 16; o; o >>= 1) m = fmaxf(m, __shfl_xor_sync(0xffffffffu, m, o));
    if ((t & 31) == 0) sh[t >> 5] = m;
    __syncthreads();
    if (t == 0) {
        float mm = sh[0];
#pragma unroll
        for (int i = 1; i < 8; i++) mm = fmaxf(mm, sh[i]);
        sh[32] = mm;
    }
    __syncthreads();
    m = sh[32];
    float s = 0.f;
#pragma unroll
    for (int u = 0; u < 4; u++) { v[u] = __expf(v[u] - m); s += v[u]; }
#pragma unroll
    for (int o = 16; o; o >>= 1) s += __shfl_xor_sync(0xffffffffu, s, o);
    __syncthreads();
    if ((t & 31) == 0) sh[t >> 5] = s;
    __syncthreads();
    if (t == 0) {
        float ss = 0.f;
#pragma unroll
        for (int i = 0; i < 8; i++) ss += sh[i];
        sh[32] = ss;
    }
    __syncthreads();
    const float inv = 1.0f / sh[32];
    *(float4*)&g_beta[(long)b * NP + t * 4] =
        make_float4(v[0] * inv, v[1] * inv, v[2] * inv, v[3] * inv);
}

// ---------------------------------------------------------------------------
// Stage 5+7 MERGED: blocks 0..15 -> alpha softmax; 16..19 -> beta_mean.
// ---------------------------------------------------------------------------
__global__ __launch_bounds__(256) void k_tail2(float* __restrict__ out_alpha,
                                               float* __restrict__ out_beta) {
    const int t = threadIdx.x;
    if (blockIdx.x < NB) {
        const int b = blockIdx.x;
        float v[4];
#pragma unroll
        for (int u = 0; u < 4; u++) {
            const int p = t + u * 256;
            float s = 0.f;
#pragma unroll
            for (int mt = 0; mt < 4; mt++) s += g_rm_part[(b * 4 + mt) * NP + p];
            v[u] = s * (1.0f / 256.0f);
        }
        __shared__ float sh[33];
        float m = fmaxf(fmaxf(v[0], v[1]), fmaxf(v[2], v[3]));
#pragma unroll
        for (int o = 16; o; o >>= 1) m = fmaxf(m, __shfl_xor_sync(0xffffffffu, m, o));
        if ((t & 31) == 0) sh[t >> 5] = m;
        __syncthreads();
        if (t == 0) {
            float mm = sh[0];
#pragma unroll
            for (int i = 1; i < 8; i++) mm = fmaxf(mm, sh[i]);
            sh[32] = mm;
        }
        __syncthreads();
        m = sh[32];
        float s = 0.f;
#pragma unroll
        for (int u = 0; u < 4; u++) { v[u] = __expf(v[u] - m); s += v[u]; }
#pragma unroll
        for (int o = 16; o; o >>= 1) s += __shfl_xor_sync(0xffffffffu, s, o);
        __syncthreads();
        if ((t & 31) == 0) sh[t >> 5] = s;
        __syncthreads();
        if (t == 0) {
            float ss = 0.f;
#pragma unroll
            for (int i = 0; i < 8; i++) ss += sh[i];
            sh[32] = ss;
        }
        __syncthreads();
        const float inv = 1.0f / sh[32];
#pragma unroll
        for (int u = 0; u < 4; u++) out_alpha[(long)b * NP + t + u * 256] = v[u] * inv;
    } else {
        const int qi = (blockIdx.x - NB) * 256 + t;
        float s = 0.f;
#pragma unroll
        for (int b = 0; b < NB; b++) s += g_beta[(long)b * NP + qi];
        s *= (1.0f / (float)NB);
#pragma unroll
        for (int rr = 0; rr < NB; rr++) out_beta[(long)rr * NP + qi] = s;
    }
}

// ---------------------------------------------------------------------------
extern "C" void kernel_launch(void* const* d_in, const int* in_sizes, int n_in,
                              void* d_out, int out_size) {
    const float* f_q     = (const float*)d_in[0];
    const float* f_s     = (const float*)d_in[1];
    const float* w_cca_q = (const float*)d_in[2];
    const float* w_cca_k = (const float*)d_in[3];
    const float* w_cca_v = (const float*)d_in[4];
    const float* w_sca_q = (const float*)d_in[5];
    const float* w_sca_k = (const float*)d_in[6];
    const float* lam     = (const float*)d_in[7];
    float* out = (float*)d_out;

    cudaFuncSetAttribute(k_gemm1f, cudaFuncAttributeMaxDynamicSharedMemorySize, G1_SMEM);
    cudaFuncSetAttribute(k_gemm2, cudaFuncAttributeMaxDynamicSharedMemorySize, GEMM_SMEM);

    k_prep<<<512, 256>>>(f_s, w_sca_k);
    k_trans<<<dim3(32, 16), 256>>>(w_cca_v);
    k_gemm1f<<<dim3(8, NB), 512, G1_SMEM>>>(f_q, w_cca_q, w_cca_k);
    k_gemm2<<<dim3(8, 4, NB), 256, GEMM_SMEM>>>(f_q, w_sca_q, lam, out);
    k_betafused<<<NB, 256>>>(w_sca_k);
    k_tail2<<<NB + 4, 256>>>(out + OUT_ALPHA, out + OUT_BETA);
}

// round 15
// speedup vs baseline: 1.2023x; 1.2023x over previous
#include <cuda_runtime.h>
#include <cuda_bf16.h>
#include <math.h>

// Problem constants
static constexpr int NB = 16;           // B_Nq == B_Ns
static constexpr int NC = 512;          // C
static constexpr int NP = 1024;         // H*W
static constexpr long CP = (long)NC * NP;            // 524288
static constexpr long OUT_ALPHA = (long)NB * CP;     // 8388608
static constexpr long OUT_BETA  = OUT_ALPHA + (long)NB * NP;

// Scratch (device globals; allocation-free kernel_launch)
__device__ float          g_fsmean[NC * NP];          // mean_b f_s (fp32)
__device__ __nv_bfloat16  g_fsmean_h[NC * NP];        // bf16 [d,p] (GEMM1 B)
__device__ __nv_bfloat16  g_fsvT[NP * NC];            // bf16 [p,d] = wv[d]*fsmean[d,p]
__device__ __nv_bfloat16  g_Sh[(long)NB * NC * NC];   // softmaxed Ac (bf16)
__device__ float          g_ksbar[NC];
__device__ float          g_rm_part[NB * 4 * NP];
__device__ float          g_qb_part[NB * 8 * NC];
__device__ float          g_beta[NB * NP];            // beta

// ---------------------------------------------------------------------------
// PTX helpers
// ---------------------------------------------------------------------------
__device__ __forceinline__ unsigned sptr(const void* p) {
    return (unsigned)__cvta_generic_to_shared(p);
}
__device__ __forceinline__ void ldsm_x4(unsigned& r0, unsigned& r1, unsigned& r2, unsigned& r3,
                                        unsigned addr) {
    asm volatile("ldmatrix.sync.aligned.m8n8.x4.shared.b16 {%0,%1,%2,%3}, [%4];"
                 : "=r"(r0), "=r"(r1), "=r"(r2), "=r"(r3) : "r"(addr));
}
__device__ __forceinline__ void mma_bf16(float c[4], const unsigned a[4], const unsigned b[2]) {
    asm volatile(
        "mma.sync.aligned.m16n8k16.row.col.f32.bf16.bf16.f32 "
        "{%0,%1,%2,%3}, {%4,%5,%6,%7}, {%8,%9}, {%0,%1,%2,%3};"
        : "+f"(c[0]), "+f"(c[1]), "+f"(c[2]), "+f"(c[3])
        : "r"(a[0]), "r"(a[1]), "r"(a[2]), "r"(a[3]), "r"(b[0]), "r"(b[1]));
}
__device__ __forceinline__ void cpa16(const void* s, const void* g) {
    unsigned saddr = sptr(s);
    asm volatile("cp.async.cg.shared.global [%0], [%1], 16;" :: "r"(saddr), "l"(g));
}
__device__ __forceinline__ void cpa_commit() { asm volatile("cp.async.commit_group;"); }
__device__ __forceinline__ void cpa_wait2()  { asm volatile("cp.async.wait_group 2;"); }
__device__ __forceinline__ void cpa_wait1()  { asm volatile("cp.async.wait_group 1;"); }
__device__ __forceinline__ void cpa_wait0()  { asm volatile("cp.async.wait_group 0;"); }

__device__ __forceinline__ unsigned pack_bf2(float lo, float hi) {
    __nv_bfloat162 h = __floats2bfloat162_rn(lo, hi);
    return *(unsigned*)&h;
}

// ---------------------------------------------------------------------------
// Stage 1 (prep): block == one channel row c. fs_mean, bf16 copy, ksbar.
// ---------------------------------------------------------------------------
__global__ __launch_bounds__(256) void k_prep(const float* __restrict__ fs,
                                              const float* __restrict__ wsk) {
    const int c = blockIdx.x;
    const int t = threadIdx.x;
    const int i4 = c * 256 + t;
    const float4* f4 = (const float4*)fs;
    float4 a = make_float4(0.f, 0.f, 0.f, 0.f);
#pragma unroll
    for (int b = 0; b < NB; b++) {
        float4 v = f4[(long)b * (CP / 4) + i4];
        a.x += v.x; a.y += v.y; a.z += v.z; a.w += v.w;
    }
    const float s = 1.0f / (float)NB;
    a.x *= s; a.y *= s; a.z *= s; a.w *= s;
    ((float4*)g_fsmean)[i4] = a;
    ((uint2*)g_fsmean_h)[i4] = make_uint2(pack_bf2(a.x, a.y), pack_bf2(a.z, a.w));

    float rs = a.x + a.y + a.z + a.w;
    __shared__ float sh[8];
#pragma unroll
    for (int o = 16; o; o >>= 1) rs += __shfl_xor_sync(0xffffffffu, rs, o);
    if ((t & 31) == 0) sh[t >> 5] = rs;
    __syncthreads();
    if (t == 0) {
        float tot = 0.f;
#pragma unroll
        for (int i = 0; i < 8; i++) tot += sh[i];
        g_ksbar[c] = wsk[c] * tot * (1.0f / (float)NP);
    }
}

// ---------------------------------------------------------------------------
// Stage 1c: fsvT[p,d] = wv[d]*fsmean[d,p]  (bf16, K-major for GEMM2 B)
// ---------------------------------------------------------------------------
__global__ __launch_bounds__(256) void k_trans(const float* __restrict__ wv) {
    __shared__ float tile[32][33];
    const int p0 = blockIdx.x * 32, d0 = blockIdx.y * 32;
    const int tx = threadIdx.x & 31, ty = threadIdx.x >> 5;   // ty 0..7
#pragma unroll
    for (int r = 0; r < 4; r++) {
        const int d = d0 + ty + r * 8;
        tile[ty + r * 8][tx] = g_fsmean[(long)d * NP + p0 + tx] * wv[d];
    }
    __syncthreads();
#pragma unroll
    for (int r = 0; r < 4; r++) {
        const int p = p0 + ty + r * 8;
        g_fsvT[(long)p * NC + d0 + tx] = __float2bfloat16_rn(tile[tx][ty + r * 8]);
    }
}

// ---------------------------------------------------------------------------
// Stage 2: FUSED GEMM1 + row softmax (round-7 proven).
//   CTA tile 64(c) x 512(d), 512 threads (16 warps: wm=w&1, wn=w>>1).
// ---------------------------------------------------------------------------
static constexpr int G1_BKH = 40;                       // padded halves per row
static constexpr int G1_AH = 64 * G1_BKH;               // 2560 halves / A stage
static constexpr int G1_BH = 512 * G1_BKH;              // 20480 halves / B stage
static constexpr int G1_STG_H = G1_AH + G1_BH;          // 23040
static constexpr int G1_SMEM = 3 * G1_STG_H * 2 + 4096; // + softmax red buffers

__global__ __launch_bounds__(512, 1) void k_gemm1f(const float* __restrict__ fq,
                                                   const float* __restrict__ wq,
                                                   const float* __restrict__ wk) {
    extern __shared__ __align__(16) __nv_bfloat16 smh[];
    const int b  = blockIdx.y;
    const int m0 = blockIdx.x * 64;
    const float* A = fq + (long)b * CP + (long)m0 * NP;
    const __nv_bfloat16* B = g_fsmean_h;
    const int t = threadIdx.x;
    const int w = t >> 5, l = t & 31;
    const int wm = w & 1, wn = w >> 1;     // 2 x 8 warp grid
    const int r = l >> 2, q = l & 3;

    unsigned aoff[2], boff[4];
#pragma unroll
    for (int mi = 0; mi < 2; mi++)
        aoff[mi] = ((wm * 32 + mi * 16 + (l & 15)) * G1_BKH + (l >> 4) * 8) * 2;
#pragma unroll
    for (int g = 0; g < 4; g++)
        boff[g] = ((wn * 64 + g * 16 + ((l >> 4) << 3) + (l & 7)) * G1_BKH + ((l >> 3) & 1) * 8) * 2;
    const unsigned smb = sptr(smh);

    const int arow = t >> 3, akc = (t & 7) * 4;
    float acc[2][8][4] = {};

    auto ldA = [&](int k0) -> float4 {
        return *(const float4*)(A + (long)arow * NP + k0 + akc);
    };
    auto stA = [&](int stg, float4 v) {
        *(uint2*)((char*)(smh + stg * G1_STG_H) + (arow * G1_BKH + akc) * 2) =
            make_uint2(pack_bf2(v.x, v.y), pack_bf2(v.z, v.w));
    };
    auto ldB = [&](int stg, int k0) {
        __nv_bfloat16* bs = smh + stg * G1_STG_H + G1_AH;
#pragma unroll
        for (int u = 0; u < 4; u++) {
            const int idx = u * 512 + t;
            const int row = idx >> 2, kc = (idx & 3) * 8;
            cpa16(bs + row * G1_BKH + kc, B + (long)row * NP + k0 + kc);
        }
        cpa_commit();
    };

    const int NK = NP / 32;   // 32
    float4 a0 = ldA(0);
    ldB(0, 0);
    float4 a1 = ldA(32);
    ldB(1, 32);
    stA(0, a0);
    stA(1, a1);
    float4 ar = ldA(64);
    ldB(2, 64);

    for (int ks = 0; ks < NK; ks++) {
        const int rem = NK - 1 - ks;
        if (rem >= 2) cpa_wait2(); else if (rem == 1) cpa_wait1(); else cpa_wait0();
        __syncthreads();
        if (ks + 2 < NK) stA((ks + 2) % 3, ar);
        const int stg = ks % 3;
        const unsigned ab = smb + stg * (G1_STG_H * 2);
        const unsigned bb = ab + G1_AH * 2;
#pragma unroll
        for (int kk = 0; kk < 2; kk++) {
            unsigned af[2][4], bf[8][2];
#pragma unroll
            for (int mi = 0; mi < 2; mi++)
                ldsm_x4(af[mi][0], af[mi][1], af[mi][2], af[mi][3], ab + aoff[mi] + kk * 32);
#pragma unroll
            for (int g = 0; g < 4; g++)
                ldsm_x4(bf[2 * g][0], bf[2 * g][1], bf[2 * g + 1][0], bf[2 * g + 1][1],
                        bb + boff[g] + kk * 32);
#pragma unroll
            for (int mi = 0; mi < 2; mi++)
#pragma unroll
                for (int ni = 0; ni < 8; ni++)
                    mma_bf16(acc[mi][ni], af[mi], bf[ni]);
        }
        if (ks + 3 < NK) ar = ldA((ks + 3) * 32);
        if (ks + 2 < NK) ldB((ks + 2) % 3, (ks + 2) * 32);
    }

    // ---- fused softmax epilogue ----
    float* red  = (float*)(smh + 3 * G1_STG_H);   // [64][8]
    float* red2 = red + 512;                      // [64][8]
    float rw[2][2], cw[8][2];
#pragma unroll
    for (int mi = 0; mi < 2; mi++)
#pragma unroll
    for (int h = 0; h < 2; h++)
        rw[mi][h] = wq[m0 + wm * 32 + mi * 16 + h * 8 + r] * (1.0f / (float)NP);
#pragma unroll
    for (int ni = 0; ni < 8; ni++) {
        cw[ni][0] = wk[wn * 64 + ni * 8 + q * 2 + 0];
        cw[ni][1] = wk[wn * 64 + ni * 8 + q * 2 + 1];
    }
#pragma unroll
    for (int mi = 0; mi < 2; mi++)
#pragma unroll
    for (int ni = 0; ni < 8; ni++)
#pragma unroll
    for (int h = 0; h < 2; h++) {
        acc[mi][ni][h * 2 + 0] *= rw[mi][h] * cw[ni][0];
        acc[mi][ni][h * 2 + 1] *= rw[mi][h] * cw[ni][1];
    }
#pragma unroll
    for (int mi = 0; mi < 2; mi++)
#pragma unroll
    for (int h = 0; h < 2; h++) {
        float m = acc[mi][0][h * 2];
#pragma unroll
        for (int ni = 0; ni < 8; ni++)
            m = fmaxf(m, fmaxf(acc[mi][ni][h * 2], acc[mi][ni][h * 2 + 1]));
        m = fmaxf(m, __shfl_xor_sync(0xffffffffu, m, 1));
        m = fmaxf(m, __shfl_xor_sync(0xffffffffu, m, 2));
        if (q == 0) red[(wm * 32 + mi * 16 + h * 8 + r) * 8 + wn] = m;
    }
    __syncthreads();
    float rmax[2][2];
#pragma unroll
    for (int mi = 0; mi < 2; mi++)
#pragma unroll
    for (int h = 0; h < 2; h++) {
        const float* rr = red + (wm * 32 + mi * 16 + h * 8 + r) * 8;
        float m = rr[0];
#pragma unroll
        for (int i = 1; i < 8; i++) m = fmaxf(m, rr[i]);
        rmax[mi][h] = m;
    }
#pragma unroll
    for (int mi = 0; mi < 2; mi++)
#pragma unroll
    for (int h = 0; h < 2; h++) {
        float s = 0.f;
#pragma unroll
        for (int ni = 0; ni < 8; ni++) {
            float e0 = __expf(acc[mi][ni][h * 2 + 0] - rmax[mi][h]);
            float e1 = __expf(acc[mi][ni][h * 2 + 1] - rmax[mi][h]);
            acc[mi][ni][h * 2 + 0] = e0;
            acc[mi][ni][h * 2 + 1] = e1;
            s += e0 + e1;
        }
        s += __shfl_xor_sync(0xffffffffu, s, 1);
        s += __shfl_xor_sync(0xffffffffu, s, 2);
        if (q == 0) red2[(wm * 32 + mi * 16 + h * 8 + r) * 8 + wn] = s;
    }
    __syncthreads();
    __nv_bfloat16* D = g_Sh + (long)b * NC * NC;
#pragma unroll
    for (int mi = 0; mi < 2; mi++)
#pragma unroll
    for (int h = 0; h < 2; h++) {
        const int c = m0 + wm * 32 + mi * 16 + h * 8 + r;
        const float* rr = red2 + (c - m0) * 8;
        float s = 0.f;
#pragma unroll
        for (int i = 0; i < 8; i++) s += rr[i];
        const float inv = 1.0f / s;
#pragma unroll
        for (int ni = 0; ni < 8; ni++)
            *(unsigned*)&D[(long)c * NC + wn * 64 + ni * 8 + q * 2] =
                pack_bf2(acc[mi][ni][h * 2] * inv, acc[mi][ni][h * 2 + 1] * inv);
    }
}

// ---------------------------------------------------------------------------
// Stage 4: GEMM2 (NT) bf16 — EXACT round-7 configuration (best measured).
// ---------------------------------------------------------------------------
static constexpr int BKH = 72;
static constexpr int THALF = 128 * BKH;
static constexpr int STG_H = 2 * THALF;
static constexpr int GEMM_SMEM = 3 * STG_H * 2;   // 110592 bytes

__global__ __launch_bounds__(256, 2) void k_gemm2(const float* __restrict__ fq,
                                                  const float* __restrict__ wsq,
                                                  const float* __restrict__ lamp,
                                                  float* __restrict__ out) {
    extern __shared__ __align__(16) __nv_bfloat16 smh[];
    const int b  = blockIdx.z;
    const int m0 = blockIdx.y * 128;
    const int n0 = blockIdx.x * 128;
    const __nv_bfloat16* A = g_Sh + (long)b * NC * NC;
    const __nv_bfloat16* B = g_fsvT;
    const int t = threadIdx.x;
    const int w = t >> 5, l = t & 31;
    const int wm = w & 3, wn = w >> 2;
    const int r = l >> 2, q = l & 3;

    unsigned aoff[2], boff[4];
#pragma unroll
    for (int mi = 0; mi < 2; mi++)
        aoff[mi] = ((wm * 32 + mi * 16 + (l & 15)) * BKH + (l >> 4) * 8) * 2;
#pragma unroll
    for (int g = 0; g < 4; g++)
        boff[g] = ((wn * 64 + g * 16 + ((l >> 4) << 3) + (l & 7)) * BKH + ((l >> 3) & 1) * 8) * 2;
    const unsigned smb = sptr(smh);

    float acc[2][8][4] = {};

    auto load_stage = [&](int stg, int k0) {
        __nv_bfloat16* as = smh + stg * STG_H;
        __nv_bfloat16* bs = as + THALF;
#pragma unroll
        for (int u = 0; u < 4; u++) {
            const int idx = u * 256 + t;
            const int row = idx >> 3, kc = (idx & 7) * 8;
            cpa16(as + row * BKH + kc, A + (long)(m0 + row) * NC + k0 + kc);
            cpa16(bs + row * BKH + kc, B + (long)(n0 + row) * NC + k0 + kc);
        }
        cpa_commit();
    };

    const int NK = NC / 64;   // 8
    load_stage(0, 0);
    load_stage(1, 64);

    int stg = 0;
    for (int ks = 0; ks < NK; ks++) {
        if (ks + 1 < NK) cpa_wait1(); else cpa_wait0();
        __syncthreads();
        const unsigned ab = smb + stg * (STG_H * 2);
        const unsigned bb = ab + THALF * 2;
#pragma unroll
        for (int kk = 0; kk < 4; kk++) {
            unsigned af[2][4], bf[8][2];
#pragma unroll
            for (int mi = 0; mi < 2; mi++)
                ldsm_x4(af[mi][0], af[mi][1], af[mi][2], af[mi][3], ab + aoff[mi] + kk * 32);
#pragma unroll
            for (int g = 0; g < 4; g++)
                ldsm_x4(bf[2 * g][0], bf[2 * g][1], bf[2 * g + 1][0], bf[2 * g + 1][1],
                        bb + boff[g] + kk * 32);
#pragma unroll
            for (int mi = 0; mi < 2; mi++)
#pragma unroll
                for (int ni = 0; ni < 8; ni++)
                    mma_bf16(acc[mi][ni], af[mi], bf[ni]);
        }
        if (ks + 2 < NK) load_stage((ks + 2) % 3, (ks + 2) * 64);
        stg = (stg + 1) % 3;
    }

    // ---- fused epilogue ----
    const float lam = *lamp;
    float rmloc[8][2] = {};
    float qbloc[2][2] = {};
#pragma unroll
    for (int mi = 0; mi < 2; mi++)
#pragma unroll
    for (int h = 0; h < 2; h++) {
        const int c = m0 + wm * 32 + mi * 16 + h * 8 + r;
        const float wc = wsq[c];
        const float wk2 = wc * g_ksbar[c];
        const float* fr = fq + (long)b * CP + (long)c * NP;
        float* orow = out + (long)b * CP + (long)c * NP;
        float qsum = 0.f;
#pragma unroll
        for (int ni = 0; ni < 8; ni++) {
            const int p = n0 + wn * 64 + ni * 8 + q * 2;
            const float v0 = acc[mi][ni][h * 2 + 0];
            const float v1 = acc[mi][ni][h * 2 + 1];
            const float2 f = *(const float2*)&fr[p];
            *(float2*)&orow[p] = make_float2(fmaf(lam, v0, f.x), fmaf(lam, v1, f.y));
            rmloc[ni][0] += v0 * wk2;
            rmloc[ni][1] += v1 * wk2;
            qsum += v0 + v1;
        }
        qbloc[mi][h] = qsum * wc;
    }
#pragma unroll
    for (int ni = 0; ni < 8; ni++)
#pragma unroll
    for (int j = 0; j < 2; j++) {
        float v = rmloc[ni][j];
        v += __shfl_xor_sync(0xffffffffu, v, 4);
        v += __shfl_xor_sync(0xffffffffu, v, 8);
        v += __shfl_xor_sync(0xffffffffu, v, 16);
        rmloc[ni][j] = v;
    }
#pragma unroll
    for (int mi = 0; mi < 2; mi++)
#pragma unroll
    for (int h = 0; h < 2; h++) {
        float v = qbloc[mi][h];
        v += __shfl_xor_sync(0xffffffffu, v, 1);
        v += __shfl_xor_sync(0xffffffffu, v, 2);
        qbloc[mi][h] = v;
    }
    __syncthreads();
    float* stage = (float*)smh;      // reuse smem
    float* rmstage = stage;          // [4][128]
    float* qbstage = stage + 512;    // [2][128]
    if (r == 0) {
#pragma unroll
        for (int ni = 0; ni < 8; ni++) {
            rmstage[wm * 128 + wn * 64 + ni * 8 + q * 2 + 0] = rmloc[ni][0];
            rmstage[wm * 128 + wn * 64 + ni * 8 + q * 2 + 1] = rmloc[ni][1];
        }
    }
    if (q == 0) {
#pragma unroll
        for (int mi = 0; mi < 2; mi++)
#pragma unroll
        for (int h = 0; h < 2; h++)
            qbstage[wn * 128 + wm * 32 + mi * 16 + h * 8 + r] = qbloc[mi][h];
    }
    __syncthreads();
    if (t < 128) {
        const float s = rmstage[t] + rmstage[128 + t] + rmstage[256 + t] + rmstage[384 + t];
        g_rm_part[(b * 4 + blockIdx.y) * NP + blockIdx.x * 128 + t] = s;
        const float s2 = qbstage[t] + qbstage[128 + t];
        g_qb_part[(b * 8 + blockIdx.x) * NC + blockIdx.y * 128 + t] = s2;
    }
}

// ---------------------------------------------------------------------------
// Stage 6: FUSED beta GEMV + softmax (round-7 proven). grid=16(b), 1024 thr.
// ---------------------------------------------------------------------------
__global__ __launch_bounds__(1024) void k_betafused(const float* __restrict__ wsk) {
    __shared__ float qsw[NC];
    __shared__ float sh[33];
    const int b = blockIdx.x;
    const int t = threadIdx.x;      // == p
    if (t < NC) {
        float s = 0.f;
#pragma unroll
        for (int nt = 0; nt < 8; nt++) s += g_qb_part[(b * 8 + nt) * NC + t];
        qsw[t] = s * (1.0f / (float)NP) * wsk[t];
    }
    __syncthreads();
    float acc = 0.f;
#pragma unroll 8
    for (int c = 0; c < NC; c++)
        acc = fmaf(qsw[c], g_fsmean[(long)c * NP + t], acc);
    acc *= (1.0f / 256.0f);         // 1/(TAU*C)
    float m = acc;
#pragma unroll
    for (int o = 16; o; o >>= 1) m = fmaxf(m, __shfl_xor_sync(0xffffffffu, m, o));
    if ((t & 31) == 0) sh[t >> 5] = m;
    __syncthreads();
    if (t == 0) {
        float mm = sh[0];
#pragma unroll
        for (int i = 1; i < 32; i++) mm = fmaxf(mm, sh[i]);
        sh[32] = mm;
    }
    __syncthreads();
    m = sh[32];
    float e = __expf(acc - m);
    float s = e;
#pragma unroll
    for (int o = 16; o; o >>= 1) s += __shfl_xor_sync(0xffffffffu, s, o);
    __syncthreads();
    if ((t & 31) == 0) sh[t >> 5] = s;
    __syncthreads();
    if (t == 0) {
        float ss = 0.f;
#pragma unroll
        for (int i = 0; i < 32; i++) ss += sh[i];
        sh[32] = ss;
    }
    __syncthreads();
    g_beta[(long)b * NP + t] = e / sh[32];
}

// ---------------------------------------------------------------------------
// Stage 5+7 MERGED: blocks 0..15 -> alpha softmax; 16..19 -> beta_mean.
// ---------------------------------------------------------------------------
__global__ __launch_bounds__(256) void k_tail2(float* __restrict__ out_alpha,
                                               float* __restrict__ out_beta) {
    const int t = threadIdx.x;
    if (blockIdx.x < NB) {
        const int b = blockIdx.x;
        float v[4];
#pragma unroll
        for (int u = 0; u < 4; u++) {
            const int p = t + u * 256;
            float s = 0.f;
#pragma unroll
            for (int mt = 0; mt < 4; mt++) s += g_rm_part[(b * 4 + mt) * NP + p];
            v[u] = s * (1.0f / 256.0f);
        }
        __shared__ float sh[33];
        float m = fmaxf(fmaxf(v[0], v[1]), fmaxf(v[2], v[3]));
#pragma unroll
        for (int o = 16; o; o >>= 1) m = fmaxf(m, __shfl_xor_sync(0xffffffffu, m, o));
        if ((t & 31) == 0) sh[t >> 5] = m;
        __syncthreads();
        if (t == 0) {
            float mm = sh[0];
#pragma unroll
            for (int i = 1; i < 8; i++) mm = fmaxf(mm, sh[i]);
            sh[32] = mm;
        }
        __syncthreads();
        m = sh[32];
        float s = 0.f;
#pragma unroll
        for (int u = 0; u < 4; u++) { v[u] = __expf(v[u] - m); s += v[u]; }
#pragma unroll
        for (int o = 16; o; o >>= 1) s += __shfl_xor_sync(0xffffffffu, s, o);
        __syncthreads();
        if ((t & 31) == 0) sh[t >> 5] = s;
        __syncthreads();
        if (t == 0) {
            float ss = 0.f;
#pragma unroll
            for (int i = 0; i < 8; i++) ss += sh[i];
            sh[32] = ss;
        }
        __syncthreads();
        const float inv = 1.0f / sh[32];
#pragma unroll
        for (int u = 0; u < 4; u++) out_alpha[(long)b * NP + t + u * 256] = v[u] * inv;
    } else {
        const int qi = (blockIdx.x - NB) * 256 + t;
        float s = 0.f;
#pragma unroll
        for (int b = 0; b < NB; b++) s += g_beta[(long)b * NP + qi];
        s *= (1.0f / (float)NB);
#pragma unroll
        for (int rr = 0; rr < NB; rr++) out_beta[(long)rr * NP + qi] = s;
    }
}

// ---------------------------------------------------------------------------
extern "C" void kernel_launch(void* const* d_in, const int* in_sizes, int n_in,
                              void* d_out, int out_size) {
    const float* f_q     = (const float*)d_in[0];
    const float* f_s     = (const float*)d_in[1];
    const float* w_cca_q = (const float*)d_in[2];
    const float* w_cca_k = (const float*)d_in[3];
    const float* w_cca_v = (const float*)d_in[4];
    const float* w_sca_q = (const float*)d_in[5];
    const float* w_sca_k = (const float*)d_in[6];
    const float* lam     = (const float*)d_in[7];
    float* out = (float*)d_out;

    cudaFuncSetAttribute(k_gemm1f, cudaFuncAttributeMaxDynamicSharedMemorySize, G1_SMEM);
    cudaFuncSetAttribute(k_gemm2, cudaFuncAttributeMaxDynamicSharedMemorySize, GEMM_SMEM);

    k_prep<<<512, 256>>>(f_s, w_sca_k);
    k_trans<<<dim3(32, 16), 256>>>(w_cca_v);
    k_gemm1f<<<dim3(8, NB), 512, G1_SMEM>>>(f_q, w_cca_q, w_cca_k);
    k_gemm2<<<dim3(8, 4, NB), 256, GEMM_SMEM>>>(f_q, w_sca_q, lam, out);
    k_betafused<<<NB, 1024>>>(w_sca_k);
    k_tail2<<<NB + 4, 256>>>(out + OUT_ALPHA, out + OUT_BETA);
}

// round 16
// speedup vs baseline: 1.3078x; 1.0877x over previous
#include <cuda_runtime.h>
#include <cuda_bf16.h>
#include <math.h>

// Problem constants
static constexpr int NB = 16;           // B_Nq == B_Ns
static constexpr int NC = 512;          // C
static constexpr int NP = 1024;         // H*W
static constexpr long CP = (long)NC * NP;            // 524288
static constexpr long OUT_ALPHA = (long)NB * CP;     // 8388608
static constexpr long OUT_BETA  = OUT_ALPHA + (long)NB * NP;

// Scratch (device globals; allocation-free kernel_launch)
__device__ float          g_fsmean[NC * NP];          // mean_b f_s (fp32)
__device__ __nv_bfloat16  g_fsmean_h[NC * NP];        // bf16 [d,p] (GEMM1 B)
__device__ __nv_bfloat16  g_fsvT[NP * NC];            // bf16 [p,d] = wv[d]*fsmean[d,p]
__device__ __nv_bfloat16  g_Sh[(long)NB * NC * NC];   // softmaxed Ac (bf16)
__device__ float          g_ksbar[NC];
__device__ float          g_rm_part[NB * 4 * NP];
__device__ float          g_qb_part[NB * 8 * NC];
__device__ float          g_beta[NB * NP];            // beta

// ---------------------------------------------------------------------------
// PTX helpers
// ---------------------------------------------------------------------------
__device__ __forceinline__ unsigned sptr(const void* p) {
    return (unsigned)__cvta_generic_to_shared(p);
}
__device__ __forceinline__ void ldsm_x4(unsigned& r0, unsigned& r1, unsigned& r2, unsigned& r3,
                                        unsigned addr) {
    asm volatile("ldmatrix.sync.aligned.m8n8.x4.shared.b16 {%0,%1,%2,%3}, [%4];"
                 : "=r"(r0), "=r"(r1), "=r"(r2), "=r"(r3) : "r"(addr));
}
__device__ __forceinline__ void mma_bf16(float c[4], const unsigned a[4], const unsigned b[2]) {
    asm volatile(
        "mma.sync.aligned.m16n8k16.row.col.f32.bf16.bf16.f32 "
        "{%0,%1,%2,%3}, {%4,%5,%6,%7}, {%8,%9}, {%0,%1,%2,%3};"
        : "+f"(c[0]), "+f"(c[1]), "+f"(c[2]), "+f"(c[3])
        : "r"(a[0]), "r"(a[1]), "r"(a[2]), "r"(a[3]), "r"(b[0]), "r"(b[1]));
}
__device__ __forceinline__ void cpa16(const void* s, const void* g) {
    unsigned saddr = sptr(s);
    asm volatile("cp.async.cg.shared.global [%0], [%1], 16;" :: "r"(saddr), "l"(g));
}
__device__ __forceinline__ void cpa_commit() { asm volatile("cp.async.commit_group;"); }
__device__ __forceinline__ void cpa_wait2()  { asm volatile("cp.async.wait_group 2;"); }
__device__ __forceinline__ void cpa_wait1()  { asm volatile("cp.async.wait_group 1;"); }
__device__ __forceinline__ void cpa_wait0()  { asm volatile("cp.async.wait_group 0;"); }

__device__ __forceinline__ unsigned pack_bf2(float lo, float hi) {
    __nv_bfloat162 h = __floats2bfloat162_rn(lo, hi);
    return *(unsigned*)&h;
}
// PDL: wait for upstream grid before consuming its outputs
__device__ __forceinline__ void gds() {
#if __CUDA_ARCH__ >= 900
    cudaGridDependencySynchronize();
#endif
}

// ---------------------------------------------------------------------------
// Stage 1 (prep): block == one channel row c. fs_mean, bf16 copy, ksbar.
// ---------------------------------------------------------------------------
__global__ __launch_bounds__(256) void k_prep(const float* __restrict__ fs,
                                              const float* __restrict__ wsk) {
    const int c = blockIdx.x;
    const int t = threadIdx.x;
    const int i4 = c * 256 + t;
    const float4* f4 = (const float4*)fs;
    float4 a = make_float4(0.f, 0.f, 0.f, 0.f);
#pragma unroll
    for (int b = 0; b < NB; b++) {
        float4 v = f4[(long)b * (CP / 4) + i4];
        a.x += v.x; a.y += v.y; a.z += v.z; a.w += v.w;
    }
    const float s = 1.0f / (float)NB;
    a.x *= s; a.y *= s; a.z *= s; a.w *= s;
    ((float4*)g_fsmean)[i4] = a;
    ((uint2*)g_fsmean_h)[i4] = make_uint2(pack_bf2(a.x, a.y), pack_bf2(a.z, a.w));

    float rs = a.x + a.y + a.z + a.w;
    __shared__ float sh[8];
#pragma unroll
    for (int o = 16; o; o >>= 1) rs += __shfl_xor_sync(0xffffffffu, rs, o);
    if ((t & 31) == 0) sh[t >> 5] = rs;
    __syncthreads();
    if (t == 0) {
        float tot = 0.f;
#pragma unroll
        for (int i = 0; i < 8; i++) tot += sh[i];
        g_ksbar[c] = wsk[c] * tot * (1.0f / (float)NP);
    }
}

// ---------------------------------------------------------------------------
// Stage 1c: fsvT[p,d] = wv[d]*fsmean[d,p]  (bf16, K-major for GEMM2 B)
// ---------------------------------------------------------------------------
__global__ __launch_bounds__(256) void k_trans(const float* __restrict__ wv) {
    __shared__ float tile[32][33];
    gds();   // wait for k_prep's g_fsmean
    const int p0 = blockIdx.x * 32, d0 = blockIdx.y * 32;
    const int tx = threadIdx.x & 31, ty = threadIdx.x >> 5;   // ty 0..7
#pragma unroll
    for (int r = 0; r < 4; r++) {
        const int d = d0 + ty + r * 8;
        tile[ty + r * 8][tx] = g_fsmean[(long)d * NP + p0 + tx] * wv[d];
    }
    __syncthreads();
#pragma unroll
    for (int r = 0; r < 4; r++) {
        const int p = p0 + ty + r * 8;
        g_fsvT[(long)p * NC + d0 + tx] = __float2bfloat16_rn(tile[tx][ty + r * 8]);
    }
}

// ---------------------------------------------------------------------------
// Stage 2: FUSED GEMM1 + row softmax (round-7 proven).
//   CTA tile 64(c) x 512(d), 512 threads (16 warps: wm=w&1, wn=w>>1).
// ---------------------------------------------------------------------------
static constexpr int G1_BKH = 40;                       // padded halves per row
static constexpr int G1_AH = 64 * G1_BKH;               // 2560 halves / A stage
static constexpr int G1_BH = 512 * G1_BKH;              // 20480 halves / B stage
static constexpr int G1_STG_H = G1_AH + G1_BH;          // 23040
static constexpr int G1_SMEM = 3 * G1_STG_H * 2 + 4096; // + softmax red buffers

__global__ __launch_bounds__(512, 1) void k_gemm1f(const float* __restrict__ fq,
                                                   const float* __restrict__ wq,
                                                   const float* __restrict__ wk) {
    extern __shared__ __align__(16) __nv_bfloat16 smh[];
    gds();   // wait for k_trans (and transitively k_prep's g_fsmean_h)
    const int b  = blockIdx.y;
    const int m0 = blockIdx.x * 64;
    const float* A = fq + (long)b * CP + (long)m0 * NP;
    const __nv_bfloat16* B = g_fsmean_h;
    const int t = threadIdx.x;
    const int w = t >> 5, l = t & 31;
    const int wm = w & 1, wn = w >> 1;     // 2 x 8 warp grid
    const int r = l >> 2, q = l & 3;

    unsigned aoff[2], boff[4];
#pragma unroll
    for (int mi = 0; mi < 2; mi++)
        aoff[mi] = ((wm * 32 + mi * 16 + (l & 15)) * G1_BKH + (l >> 4) * 8) * 2;
#pragma unroll
    for (int g = 0; g < 4; g++)
        boff[g] = ((wn * 64 + g * 16 + ((l >> 4) << 3) + (l & 7)) * G1_BKH + ((l >> 3) & 1) * 8) * 2;
    const unsigned smb = sptr(smh);

    const int arow = t >> 3, akc = (t & 7) * 4;
    float acc[2][8][4] = {};

    auto ldA = [&](int k0) -> float4 {
        return *(const float4*)(A + (long)arow * NP + k0 + akc);
    };
    auto stA = [&](int stg, float4 v) {
        *(uint2*)((char*)(smh + stg * G1_STG_H) + (arow * G1_BKH + akc) * 2) =
            make_uint2(pack_bf2(v.x, v.y), pack_bf2(v.z, v.w));
    };
    auto ldB = [&](int stg, int k0) {
        __nv_bfloat16* bs = smh + stg * G1_STG_H + G1_AH;
#pragma unroll
        for (int u = 0; u < 4; u++) {
            const int idx = u * 512 + t;
            const int row = idx >> 2, kc = (idx & 3) * 8;
            cpa16(bs + row * G1_BKH + kc, B + (long)row * NP + k0 + kc);
        }
        cpa_commit();
    };

    const int NK = NP / 32;   // 32
    float4 a0 = ldA(0);
    ldB(0, 0);
    float4 a1 = ldA(32);
    ldB(1, 32);
    stA(0, a0);
    stA(1, a1);
    float4 ar = ldA(64);
    ldB(2, 64);

    for (int ks = 0; ks < NK; ks++) {
        const int rem = NK - 1 - ks;
        if (rem >= 2) cpa_wait2(); else if (rem == 1) cpa_wait1(); else cpa_wait0();
        __syncthreads();
        if (ks + 2 < NK) stA((ks + 2) % 3, ar);
        const int stg = ks % 3;
        const unsigned ab = smb + stg * (G1_STG_H * 2);
        const unsigned bb = ab + G1_AH * 2;
#pragma unroll
        for (int kk = 0; kk < 2; kk++) {
            unsigned af[2][4], bf[8][2];
#pragma unroll
            for (int mi = 0; mi < 2; mi++)
                ldsm_x4(af[mi][0], af[mi][1], af[mi][2], af[mi][3], ab + aoff[mi] + kk * 32);
#pragma unroll
            for (int g = 0; g < 4; g++)
                ldsm_x4(bf[2 * g][0], bf[2 * g][1], bf[2 * g + 1][0], bf[2 * g + 1][1],
                        bb + boff[g] + kk * 32);
#pragma unroll
            for (int mi = 0; mi < 2; mi++)
#pragma unroll
                for (int ni = 0; ni < 8; ni++)
                    mma_bf16(acc[mi][ni], af[mi], bf[ni]);
        }
        if (ks + 3 < NK) ar = ldA((ks + 3) * 32);
        if (ks + 2 < NK) ldB((ks + 2) % 3, (ks + 2) * 32);
    }

    // ---- fused softmax epilogue ----
    float* red  = (float*)(smh + 3 * G1_STG_H);   // [64][8]
    float* red2 = red + 512;                      // [64][8]
    float rw[2][2], cw[8][2];
#pragma unroll
    for (int mi = 0; mi < 2; mi++)
#pragma unroll
    for (int h = 0; h < 2; h++)
        rw[mi][h] = wq[m0 + wm * 32 + mi * 16 + h * 8 + r] * (1.0f / (float)NP);
#pragma unroll
    for (int ni = 0; ni < 8; ni++) {
        cw[ni][0] = wk[wn * 64 + ni * 8 + q * 2 + 0];
        cw[ni][1] = wk[wn * 64 + ni * 8 + q * 2 + 1];
    }
#pragma unroll
    for (int mi = 0; mi < 2; mi++)
#pragma unroll
    for (int ni = 0; ni < 8; ni++)
#pragma unroll
    for (int h = 0; h < 2; h++) {
        acc[mi][ni][h * 2 + 0] *= rw[mi][h] * cw[ni][0];
        acc[mi][ni][h * 2 + 1] *= rw[mi][h] * cw[ni][1];
    }
#pragma unroll
    for (int mi = 0; mi < 2; mi++)
#pragma unroll
    for (int h = 0; h < 2; h++) {
        float m = acc[mi][0][h * 2];
#pragma unroll
        for (int ni = 0; ni < 8; ni++)
            m = fmaxf(m, fmaxf(acc[mi][ni][h * 2], acc[mi][ni][h * 2 + 1]));
        m = fmaxf(m, __shfl_xor_sync(0xffffffffu, m, 1));
        m = fmaxf(m, __shfl_xor_sync(0xffffffffu, m, 2));
        if (q == 0) red[(wm * 32 + mi * 16 + h * 8 + r) * 8 + wn] = m;
    }
    __syncthreads();
    float rmax[2][2];
#pragma unroll
    for (int mi = 0; mi < 2; mi++)
#pragma unroll
    for (int h = 0; h < 2; h++) {
        const float* rr = red + (wm * 32 + mi * 16 + h * 8 + r) * 8;
        float m = rr[0];
#pragma unroll
        for (int i = 1; i < 8; i++) m = fmaxf(m, rr[i]);
        rmax[mi][h] = m;
    }
#pragma unroll
    for (int mi = 0; mi < 2; mi++)
#pragma unroll
    for (int h = 0; h < 2; h++) {
        float s = 0.f;
#pragma unroll
        for (int ni = 0; ni < 8; ni++) {
            float e0 = __expf(acc[mi][ni][h * 2 + 0] - rmax[mi][h]);
            float e1 = __expf(acc[mi][ni][h * 2 + 1] - rmax[mi][h]);
            acc[mi][ni][h * 2 + 0] = e0;
            acc[mi][ni][h * 2 + 1] = e1;
            s += e0 + e1;
        }
        s += __shfl_xor_sync(0xffffffffu, s, 1);
        s += __shfl_xor_sync(0xffffffffu, s, 2);
        if (q == 0) red2[(wm * 32 + mi * 16 + h * 8 + r) * 8 + wn] = s;
    }
    __syncthreads();
    __nv_bfloat16* D = g_Sh + (long)b * NC * NC;
#pragma unroll
    for (int mi = 0; mi < 2; mi++)
#pragma unroll
    for (int h = 0; h < 2; h++) {
        const int c = m0 + wm * 32 + mi * 16 + h * 8 + r;
        const float* rr = red2 + (c - m0) * 8;
        float s = 0.f;
#pragma unroll
        for (int i = 0; i < 8; i++) s += rr[i];
        const float inv = 1.0f / s;
#pragma unroll
        for (int ni = 0; ni < 8; ni++)
            *(unsigned*)&D[(long)c * NC + wn * 64 + ni * 8 + q * 2] =
                pack_bf2(acc[mi][ni][h * 2] * inv, acc[mi][ni][h * 2 + 1] * inv);
    }
}

// ---------------------------------------------------------------------------
// Stage 4: GEMM2 (NT) bf16 — EXACT round-7 configuration (best measured).
// ---------------------------------------------------------------------------
static constexpr int BKH = 72;
static constexpr int THALF = 128 * BKH;
static constexpr int STG_H = 2 * THALF;
static constexpr int GEMM_SMEM = 3 * STG_H * 2;   // 110592 bytes

__global__ __launch_bounds__(256, 2) void k_gemm2(const float* __restrict__ fq,
                                                  const float* __restrict__ wsq,
                                                  const float* __restrict__ lamp,
                                                  float* __restrict__ out) {
    extern __shared__ __align__(16) __nv_bfloat16 smh[];
    gds();   // wait for k_gemm1f's g_Sh (transitively g_fsvT, g_ksbar)
    const int b  = blockIdx.z;
    const int m0 = blockIdx.y * 128;
    const int n0 = blockIdx.x * 128;
    const __nv_bfloat16* A = g_Sh + (long)b * NC * NC;
    const __nv_bfloat16* B = g_fsvT;
    const int t = threadIdx.x;
    const int w = t >> 5, l = t & 31;
    const int wm = w & 3, wn = w >> 2;
    const int r = l >> 2, q = l & 3;

    unsigned aoff[2], boff[4];
#pragma unroll
    for (int mi = 0; mi < 2; mi++)
        aoff[mi] = ((wm * 32 + mi * 16 + (l & 15)) * BKH + (l >> 4) * 8) * 2;
#pragma unroll
    for (int g = 0; g < 4; g++)
        boff[g] = ((wn * 64 + g * 16 + ((l >> 4) << 3) + (l & 7)) * BKH + ((l >> 3) & 1) * 8) * 2;
    const unsigned smb = sptr(smh);

    float acc[2][8][4] = {};

    auto load_stage = [&](int stg, int k0) {
        __nv_bfloat16* as = smh + stg * STG_H;
        __nv_bfloat16* bs = as + THALF;
#pragma unroll
        for (int u = 0; u < 4; u++) {
            const int idx = u * 256 + t;
            const int row = idx >> 3, kc = (idx & 7) * 8;
            cpa16(as + row * BKH + kc, A + (long)(m0 + row) * NC + k0 + kc);
            cpa16(bs + row * BKH + kc, B + (long)(n0 + row) * NC + k0 + kc);
        }
        cpa_commit();
    };

    const int NK = NC / 64;   // 8
    load_stage(0, 0);
    load_stage(1, 64);

    int stg = 0;
    for (int ks = 0; ks < NK; ks++) {
        if (ks + 1 < NK) cpa_wait1(); else cpa_wait0();
        __syncthreads();
        const unsigned ab = smb + stg * (STG_H * 2);
        const unsigned bb = ab + THALF * 2;
#pragma unroll
        for (int kk = 0; kk < 4; kk++) {
            unsigned af[2][4], bf[8][2];
#pragma unroll
            for (int mi = 0; mi < 2; mi++)
                ldsm_x4(af[mi][0], af[mi][1], af[mi][2], af[mi][3], ab + aoff[mi] + kk * 32);
#pragma unroll
            for (int g = 0; g < 4; g++)
                ldsm_x4(bf[2 * g][0], bf[2 * g][1], bf[2 * g + 1][0], bf[2 * g + 1][1],
                        bb + boff[g] + kk * 32);
#pragma unroll
            for (int mi = 0; mi < 2; mi++)
#pragma unroll
                for (int ni = 0; ni < 8; ni++)
                    mma_bf16(acc[mi][ni], af[mi], bf[ni]);
        }
        if (ks + 2 < NK) load_stage((ks + 2) % 3, (ks + 2) * 64);
        stg = (stg + 1) % 3;
    }

    // ---- fused epilogue ----
    const float lam = *lamp;
    float rmloc[8][2] = {};
    float qbloc[2][2] = {};
#pragma unroll
    for (int mi = 0; mi < 2; mi++)
#pragma unroll
    for (int h = 0; h < 2; h++) {
        const int c = m0 + wm * 32 + mi * 16 + h * 8 + r;
        const float wc = wsq[c];
        const float wk2 = wc * g_ksbar[c];
        const float* fr = fq + (long)b * CP + (long)c * NP;
        float* orow = out + (long)b * CP + (long)c * NP;
        float qsum = 0.f;
#pragma unroll
        for (int ni = 0; ni < 8; ni++) {
            const int p = n0 + wn * 64 + ni * 8 + q * 2;
            const float v0 = acc[mi][ni][h * 2 + 0];
            const float v1 = acc[mi][ni][h * 2 + 1];
            const float2 f = *(const float2*)&fr[p];
            *(float2*)&orow[p] = make_float2(fmaf(lam, v0, f.x), fmaf(lam, v1, f.y));
            rmloc[ni][0] += v0 * wk2;
            rmloc[ni][1] += v1 * wk2;
            qsum += v0 + v1;
        }
        qbloc[mi][h] = qsum * wc;
    }
#pragma unroll
    for (int ni = 0; ni < 8; ni++)
#pragma unroll
    for (int j = 0; j < 2; j++) {
        float v = rmloc[ni][j];
        v += __shfl_xor_sync(0xffffffffu, v, 4);
        v += __shfl_xor_sync(0xffffffffu, v, 8);
        v += __shfl_xor_sync(0xffffffffu, v, 16);
        rmloc[ni][j] = v;
    }
#pragma unroll
    for (int mi = 0; mi < 2; mi++)
#pragma unroll
    for (int h = 0; h < 2; h++) {
        float v = qbloc[mi][h];
        v += __shfl_xor_sync(0xffffffffu, v, 1);
        v += __shfl_xor_sync(0xffffffffu, v, 2);
        qbloc[mi][h] = v;
    }
    __syncthreads();
    float* stage = (float*)smh;      // reuse smem
    float* rmstage = stage;          // [4][128]
    float* qbstage = stage + 512;    // [2][128]
    if (r == 0) {
#pragma unroll
        for (int ni = 0; ni < 8; ni++) {
            rmstage[wm * 128 + wn * 64 + ni * 8 + q * 2 + 0] = rmloc[ni][0];
            rmstage[wm * 128 + wn * 64 + ni * 8 + q * 2 + 1] = rmloc[ni][1];
        }
    }
    if (q == 0) {
#pragma unroll
        for (int mi = 0; mi < 2; mi++)
#pragma unroll
        for (int h = 0; h < 2; h++)
            qbstage[wn * 128 + wm * 32 + mi * 16 + h * 8 + r] = qbloc[mi][h];
    }
    __syncthreads();
    if (t < 128) {
        const float s = rmstage[t] + rmstage[128 + t] + rmstage[256 + t] + rmstage[384 + t];
        g_rm_part[(b * 4 + blockIdx.y) * NP + blockIdx.x * 128 + t] = s;
        const float s2 = qbstage[t] + qbstage[128 + t];
        g_qb_part[(b * 8 + blockIdx.x) * NC + blockIdx.y * 128 + t] = s2;
    }
}

// ---------------------------------------------------------------------------
// Stage 6: FUSED beta GEMV + softmax (round-7 proven). grid=16(b), 1024 thr.
// ---------------------------------------------------------------------------
__global__ __launch_bounds__(1024) void k_betafused(const float* __restrict__ wsk) {
    __shared__ float qsw[NC];
    __shared__ float sh[33];
    gds();   // wait for k_gemm2's g_qb_part
    const int b = blockIdx.x;
    const int t = threadIdx.x;      // == p
    if (t < NC) {
        float s = 0.f;
#pragma unroll
        for (int nt = 0; nt < 8; nt++) s += g_qb_part[(b * 8 + nt) * NC + t];
        qsw[t] = s * (1.0f / (float)NP) * wsk[t];
    }
    __syncthreads();
    float acc = 0.f;
#pragma unroll 8
    for (int c = 0; c < NC; c++)
        acc = fmaf(qsw[c], g_fsmean[(long)c * NP + t], acc);
    acc *= (1.0f / 256.0f);         // 1/(TAU*C)
    float m = acc;
#pragma unroll
    for (int o = 16; o; o >>= 1) m = fmaxf(m, __shfl_xor_sync(0xffffffffu, m, o));
    if ((t & 31) == 0) sh[t >> 5] = m;
    __syncthreads();
    if (t == 0) {
        float mm = sh[0];
#pragma unroll
        for (int i = 1; i < 32; i++) mm = fmaxf(mm, sh[i]);
        sh[32] = mm;
    }
    __syncthreads();
    m = sh[32];
    float e = __expf(acc - m);
    float s = e;
#pragma unroll
    for (int o = 16; o; o >>= 1) s += __shfl_xor_sync(0xffffffffu, s, o);
    __syncthreads();
    if ((t & 31) == 0) sh[t >> 5] = s;
    __syncthreads();
    if (t == 0) {
        float ss = 0.f;
#pragma unroll
        for (int i = 0; i < 32; i++) ss += sh[i];
        sh[32] = ss;
    }
    __syncthreads();
    g_beta[(long)b * NP + t] = e / sh[32];
}

// ---------------------------------------------------------------------------
// Stage 5+7 MERGED: blocks 0..15 -> alpha softmax; 16..19 -> beta_mean.
// ---------------------------------------------------------------------------
__global__ __launch_bounds__(256) void k_tail2(float* __restrict__ out_alpha,
                                               float* __restrict__ out_beta) {
    gds();   // wait for k_betafused (transitively g_rm_part)
    const int t = threadIdx.x;
    if (blockIdx.x < NB) {
        const int b = blockIdx.x;
        float v[4];
#pragma unroll
        for (int u = 0; u < 4; u++) {
            const int p = t + u * 256;
            float s = 0.f;
#pragma unroll
            for (int mt = 0; mt < 4; mt++) s += g_rm_part[(b * 4 + mt) * NP + p];
            v[u] = s * (1.0f / 256.0f);
        }
        __shared__ float sh[33];
        float m = fmaxf(fmaxf(v[0], v[1]), fmaxf(v[2], v[3]));
#pragma unroll
        for (int o = 16; o; o >>= 1) m = fmaxf(m, __shfl_xor_sync(0xffffffffu, m, o));
        if ((t & 31) == 0) sh[t >> 5] = m;
        __syncthreads();
        if (t == 0) {
            float mm = sh[0];
#pragma unroll
            for (int i = 1; i < 8; i++) mm = fmaxf(mm, sh[i]);
            sh[32] = mm;
        }
        __syncthreads();
        m = sh[32];
        float s = 0.f;
#pragma unroll
        for (int u = 0; u < 4; u++) { v[u] = __expf(v[u] - m); s += v[u]; }
#pragma unroll
        for (int o = 16; o; o >>= 1) s += __shfl_xor_sync(0xffffffffu, s, o);
        __syncthreads();
        if ((t & 31) == 0) sh[t >> 5] = s;
        __syncthreads();
        if (t == 0) {
            float ss = 0.f;
#pragma unroll
            for (int i = 0; i < 8; i++) ss += sh[i];
            sh[32] = ss;
        }
        __syncthreads();
        const float inv = 1.0f / sh[32];
#pragma unroll
        for (int u = 0; u < 4; u++) out_alpha[(long)b * NP + t + u * 256] = v[u] * inv;
    } else {
        const int qi = (blockIdx.x - NB) * 256 + t;
        float s = 0.f;
#pragma unroll
        for (int b = 0; b < NB; b++) s += g_beta[(long)b * NP + qi];
        s *= (1.0f / (float)NB);
#pragma unroll
        for (int rr = 0; rr < NB; rr++) out_beta[(long)rr * NP + qi] = s;
    }
}

// ---------------------------------------------------------------------------
// PDL launch helper: overlap launch/drain with the predecessor kernel.
// ---------------------------------------------------------------------------
template <typename K, typename... Args>
static inline void launchP(K k, dim3 grid, dim3 block, size_t smem, Args... args) {
    cudaLaunchAttribute attr[1];
    attr[0].id = cudaLaunchAttributeProgrammaticStreamSerialization;
    attr[0].val.programmaticStreamSerializationAllowed = 1;
    cudaLaunchConfig_t cfg = {};
    cfg.gridDim = grid;
    cfg.blockDim = block;
    cfg.dynamicSmemBytes = smem;
    cfg.stream = 0;
    cfg.attrs = attr;
    cfg.numAttrs = 1;
    cudaLaunchKernelEx(&cfg, k, args...);
}

// ---------------------------------------------------------------------------
extern "C" void kernel_launch(void* const* d_in, const int* in_sizes, int n_in,
                              void* d_out, int out_size) {
    const float* f_q     = (const float*)d_in[0];
    const float* f_s     = (const float*)d_in[1];
    const float* w_cca_q = (const float*)d_in[2];
    const float* w_cca_k = (const float*)d_in[3];
    const float* w_cca_v = (const float*)d_in[4];
    const float* w_sca_q = (const float*)d_in[5];
    const float* w_sca_k = (const float*)d_in[6];
    const float* lam     = (const float*)d_in[7];
    float* out = (float*)d_out;

    cudaFuncSetAttribute(k_gemm1f, cudaFuncAttributeMaxDynamicSharedMemorySize, G1_SMEM);
    cudaFuncSetAttribute(k_gemm2, cudaFuncAttributeMaxDynamicSharedMemorySize, GEMM_SMEM);

    k_prep<<<512, 256>>>(f_s, w_sca_k);
    launchP(k_trans, dim3(32, 16), dim3(256), 0, w_cca_v);
    launchP(k_gemm1f, dim3(8, NB), dim3(512), (size_t)G1_SMEM, f_q, w_cca_q, w_cca_k);
    launchP(k_gemm2, dim3(8, 4, NB), dim3(256), (size_t)GEMM_SMEM, f_q, w_sca_q, lam, out);
    launchP(k_betafused, dim3(NB), dim3(1024), 0, w_sca_k);
    launchP(k_tail2, dim3(NB + 4), dim3(256), 0, out + OUT_ALPHA, out + OUT_BETA);
}